// round 7
// baseline (speedup 1.0000x reference)
#include <cuda_runtime.h>
#include <cstdint>

#define HDIM 128
#define WDIM 128
#define CDIM 256

#define A_STRIDE 132                     // words
#define B_STRIDE 264                     // words; frag banks lc*8+lr, conflict-free
#define KCHUNK 64
#define A_WORDS (128 * A_STRIDE)         // 16896
#define B_WORDS (KCHUNK * B_STRIDE)      // 16896
#define SMEM_BYTES ((A_WORDS + 2 * B_WORDS) * 4)   // 202752

static __device__ __forceinline__ uint32_t tf32u(float x) {
    uint32_t r;
    asm("cvt.rna.tf32.f32 %0, %1;" : "=r"(r) : "f"(x));
    return r;
}
static __device__ __forceinline__ void cp16(uint32_t dst, const void* src) {
    asm volatile("cp.async.cg.shared.global [%0], [%1], 16;" :: "r"(dst), "l"(src));
}
#define CP_COMMIT() asm volatile("cp.async.commit_group;" ::: "memory")
#define CP_WAIT(n)  asm volatile("cp.async.wait_group %0;" :: "n"(n) : "memory")

static __device__ __forceinline__ void ldsm_x4(uint32_t r[4], uint32_t addr) {
    asm volatile("ldmatrix.sync.aligned.m8n8.x4.shared.b16 {%0,%1,%2,%3}, [%4];"
                 : "=r"(r[0]), "=r"(r[1]), "=r"(r[2]), "=r"(r[3]) : "r"(addr));
}
static __device__ __forceinline__ void mma_tf32(float c[4], const uint32_t a[4],
                                                uint32_t b0, uint32_t b1) {
    asm volatile(
        "mma.sync.aligned.m16n8k8.row.col.f32.tf32.tf32.f32 "
        "{%0,%1,%2,%3}, {%4,%5,%6,%7}, {%8,%9}, {%0,%1,%2,%3};"
        : "+f"(c[0]), "+f"(c[1]), "+f"(c[2]), "+f"(c[3])
        : "r"(a[0]), "r"(a[1]), "r"(a[2]), "r"(a[3]), "r"(b0), "r"(b1));
}

// ---------------------------------------------------------------------------
// Persistent. 512 thr, tile = (b, rc): D[128,256] = softmax(attn+g) @ V_t.
// A: softmax computed straight from gmem (LDG) into single tf32 buffer.
// B: V in 2 k-chunks of 64, double-buffered cp.async, 1-tile lookahead.
// Per tile: 5 __syncthreads, 2 wait_group.
// ---------------------------------------------------------------------------
__global__ void __launch_bounds__(512, 1) gt_mma(
    const float* __restrict__ attn, const float* __restrict__ V,
    const float* __restrict__ sp, const float* __restrict__ bp,
    float* __restrict__ out, int term, int ntiles)
{
    extern __shared__ uint32_t smem[];
    uint32_t* As = smem;
    uint32_t* Bb[2] = { smem + A_WORDS, smem + A_WORDS + B_WORDS };
    const uint32_t As_u = (uint32_t)__cvta_generic_to_shared(As);
    uint32_t Bu[2];
    Bu[0] = (uint32_t)__cvta_generic_to_shared(Bb[0]);
    Bu[1] = (uint32_t)__cvta_generic_to_shared(Bb[1]);

    const int tid = threadIdx.x, lane = tid & 31, wid = tid >> 5;
    const int nCta = gridDim.x;
    const float sh = sp[0], bi = bp[0];
    const size_t vstride = term ? (size_t)(WDIM * CDIM) : (size_t)CDIM;

    auto toff = [&](int t) -> size_t {
        int rc = t & 127, b = t >> 7;
        return term ? ((size_t)b * HDIM * WDIM * CDIM + (size_t)rc * CDIM)
                    : ((size_t)b * 128 + rc) * (size_t)(WDIM * CDIM);
    };
    auto issue_B = [&](int t, int chunk, int buf) {
        const float* src = V + toff(t) + (size_t)(chunk * KCHUNK) * vstride;
        #pragma unroll
        for (int i = 0; i < 8; ++i) {
            int c = i * 512 + tid;           // 4096 chunks: 64 rows x 64 q
            int row = c >> 6, q = c & 63;
            cp16(Bu[buf] + (uint32_t)row * (B_STRIDE * 4) + (uint32_t)q * 16,
                 src + (size_t)row * vstride + q * 4);
        }
        CP_COMMIT();
    };

    int t = blockIdx.x;
    if (t >= ntiles) return;

    issue_B(t, 0, 0);
    issue_B(t, 1, 1);

    const int mh = (wid & 1) * 64;
    const int nq = (wid >> 1) * 32;
    const int lr = lane >> 2, lc = lane & 3;
    const int lm_mat = lane >> 3, lm_row = lane & 7;
    const int lm_roff = (lm_mat & 1) * 8 + lm_row;
    const int lm_koff = (lm_mat >> 1) * 4;

    #pragma unroll 1
    for (; t < ntiles; t += nCta) {
        const bool last = (t + nCta >= ntiles);
        const size_t off = toff(t);
        const int rc = t & 127, b = t >> 7;
        const float* abase = attn + ((size_t)b * 128 + rc) * (size_t)(128 * 128);

        // L2 prefetch of the RMW out tile (term 2)
        if (term) {
            const float* ob = out + off;
            #pragma unroll
            for (int i = 0; i < 2; ++i) {
                int idx = i * 512 + tid;     // 1024 x 128B lines
                int row = idx >> 3, lq = idx & 7;
                asm volatile("prefetch.global.L2 [%0];"
                             :: "l"(ob + (size_t)row * vstride + lq * 32));
            }
        }

        // ---- softmax straight from gmem (no max pass; exponents bounded) ----
        #pragma unroll 1
        for (int rr = 0; rr < 8; ++rr) {
            int row = wid * 8 + rr;
            float4 v = __ldg((const float4*)(abase + row * 128 + lane * 4));
            float fr = (float)row;
            float e[4]; float s = 0.f;
            #pragma unroll
            for (int j = 0; j < 4; ++j) {
                float d = (float)(lane * 4 + j) - fr;
                float vv = (j == 0 ? v.x : j == 1 ? v.y : j == 2 ? v.z : v.w)
                           - fmaf(sh, d * d, bi);
                e[j] = __expf(vv);
                s += e[j];
            }
            #pragma unroll
            for (int o = 16; o > 0; o >>= 1) s += __shfl_xor_sync(~0u, s, o);
            float inv = 1.0f / s;
            uint4 w = make_uint4(tf32u(e[0] * inv), tf32u(e[1] * inv),
                                 tf32u(e[2] * inv), tf32u(e[3] * inv));
            *(uint4*)(As + row * A_STRIDE + lane * 4) = w;
        }

        float acc[4][4][4];
        #pragma unroll
        for (int u = 0; u < 4; ++u)
            #pragma unroll
            for (int j = 0; j < 4; ++j)
                #pragma unroll
                for (int q = 0; q < 4; ++q) acc[u][j][q] = 0.f;

        // ---- 2 k-chunks of 64 ----
        #pragma unroll 1
        for (int c = 0; c < 2; ++c) {
            if (c == 0) CP_WAIT(1);
            else { if (last) CP_WAIT(0); else CP_WAIT(1); }
            __syncthreads();     // B chunk ready; also orders As stores vs ldsm

            const uint32_t* Bsc = Bb[c];
            #pragma unroll 4
            for (int ks = 0; ks < 8; ++ks) {
                uint32_t a[4][4];
                #pragma unroll
                for (int u = 0; u < 4; ++u) {
                    uint32_t addr = As_u + (uint32_t)((mh + u * 16 + lm_roff) * A_STRIDE
                                                      + c * KCHUNK + ks * 8 + lm_koff) * 4;
                    ldsm_x4(a[u], addr);
                }
                #pragma unroll
                for (int j = 0; j < 4; ++j) {
                    const float* bp8 = (const float*)Bsc + (ks * 8 + lc) * B_STRIDE
                                       + nq + j * 8 + lr;
                    uint32_t b0 = tf32u(bp8[0]);
                    uint32_t b1 = tf32u(bp8[4 * B_STRIDE]);
                    #pragma unroll
                    for (int u = 0; u < 4; ++u)
                        mma_tf32(acc[u][j], a[u], b0, b1);
                }
            }
            __syncthreads();     // all warps done with buf c
            if (!last) issue_B(t + nCta, c, c);
        }

        // ---- epilogue ----
        float* obase = out + off;
        #pragma unroll
        for (int u = 0; u < 4; ++u) {
            #pragma unroll
            for (int j = 0; j < 4; ++j) {
                int r0 = mh + u * 16 + lr;
                int col = nq + j * 8 + lc * 2;
                float* p0 = obase + (size_t)r0 * vstride + col;
                float* p1 = p0 + 8 * vstride;
                float2 v0 = make_float2(acc[u][j][0], acc[u][j][1]);
                float2 v1 = make_float2(acc[u][j][2], acc[u][j][3]);
                if (term) {
                    float2 c0 = *(float2*)p0, c1 = *(float2*)p1;
                    v0.x += c0.x; v0.y += c0.y;
                    v1.x += c1.x; v1.y += c1.y;
                }
                *(float2*)p0 = v0;
                *(float2*)p1 = v1;
            }
        }
        __syncthreads();         // epilogue/As reads settled before next softmax
    }
}

extern "C" void kernel_launch(void* const* d_in, const int* in_sizes, int n_in,
                              void* d_out, int out_size)
{
    const float* attn_x = (const float*)d_in[1];
    const float* attn_y = (const float*)d_in[2];
    const float* V      = (const float*)d_in[3];
    const float* sh     = (const float*)d_in[4];
    const float* bi     = (const float*)d_in[5];
    float* out          = (float*)d_out;

    const int B = in_sizes[3] / (HDIM * WDIM * CDIM);
    const int ntiles = B * 128;

    int nsm = 148;
    cudaDeviceGetAttribute(&nsm, cudaDevAttrMultiProcessorCount, 0);
    int grid = nsm < ntiles ? nsm : ntiles;

    cudaFuncSetAttribute(gt_mma, cudaFuncAttributeMaxDynamicSharedMemorySize, SMEM_BYTES);

    gt_mma<<<grid, 512, SMEM_BYTES>>>(attn_x, V, sh, bi, out, 0, ntiles);
    gt_mma<<<grid, 512, SMEM_BYTES>>>(attn_y, V, sh, bi, out, 1, ntiles);
}

// round 8
// speedup vs baseline: 1.2004x; 1.2004x over previous
#include <cuda_runtime.h>
#include <cstdint>

#define HDIM 128
#define WDIM 128
#define CDIM 256

#define A_STRIDE 132                     // words
#define B_STRIDE 264                     // words; frag banks lc*8+lr, conflict-free
#define KCHUNK 16
#define NCHUNK 8                         // 128 / KCHUNK
#define A_WORDS (128 * A_STRIDE)         // 16896
#define B_WORDS (KCHUNK * B_STRIDE)      // 4224 per buffer
#define SMEM_BYTES ((2 * A_WORDS + 4 * B_WORDS) * 4)   // 202752

static __device__ __forceinline__ uint32_t tf32u(float x) {
    uint32_t r;
    asm("cvt.rna.tf32.f32 %0, %1;" : "=r"(r) : "f"(x));
    return r;
}
static __device__ __forceinline__ void cp16(uint32_t dst, const void* src) {
    asm volatile("cp.async.cg.shared.global [%0], [%1], 16;" :: "r"(dst), "l"(src));
}
#define CP_COMMIT() asm volatile("cp.async.commit_group;" ::: "memory")
#define CP_WAIT(n)  asm volatile("cp.async.wait_group %0;" :: "n"(n) : "memory")

static __device__ __forceinline__ void ldsm_x4(uint32_t r[4], uint32_t addr) {
    asm volatile("ldmatrix.sync.aligned.m8n8.x4.shared.b16 {%0,%1,%2,%3}, [%4];"
                 : "=r"(r[0]), "=r"(r[1]), "=r"(r[2]), "=r"(r[3]) : "r"(addr));
}
static __device__ __forceinline__ void mma_tf32(float c[4], const uint32_t a[4],
                                                uint32_t b0, uint32_t b1) {
    asm volatile(
        "mma.sync.aligned.m16n8k8.row.col.f32.tf32.tf32.f32 "
        "{%0,%1,%2,%3}, {%4,%5,%6,%7}, {%8,%9}, {%0,%1,%2,%3};"
        : "+f"(c[0]), "+f"(c[1]), "+f"(c[2]), "+f"(c[3])
        : "r"(a[0]), "r"(a[1]), "r"(a[2]), "r"(a[3]), "r"(b0), "r"(b1));
}

// ---------------------------------------------------------------------------
// Persistent. 512 thr, tile = (b, rc): D[128,256] = softmax(attn+g) @ V_t.
// A: cp.async raw -> in-place softmax to tf32, double-buffered, 1-tile lookahead.
// B: V in 8 k-chunks of 16, 4-buffer ring, issued 3 chunks ahead.
// Steady-state cp.async group FIFO (per tile):
//   head wait(3): A(t) already drained (no-op)
//   c0..c2 wait(3), c3..c7 wait(2); chunk c issues B(t,c+3) / B(t+1,c-5)
//   A(t+1) issued after softmax bar.  Last tile: c0..5 wait(2), c6 w(1), c7 w(0).
// ---------------------------------------------------------------------------
__global__ void __launch_bounds__(512, 1) gt_mma(
    const float* __restrict__ attn, const float* __restrict__ V,
    const float* __restrict__ sp, const float* __restrict__ bp,
    float* __restrict__ out, int term, int ntiles)
{
    extern __shared__ uint32_t smem[];
    uint32_t* Ab[2] = { smem, smem + A_WORDS };
    uint32_t* Bb = smem + 2 * A_WORDS;               // 4 ring buffers
    uint32_t Au[2];
    Au[0] = (uint32_t)__cvta_generic_to_shared(Ab[0]);
    Au[1] = (uint32_t)__cvta_generic_to_shared(Ab[1]);
    const uint32_t Bu = (uint32_t)__cvta_generic_to_shared(Bb);

    const int tid = threadIdx.x, lane = tid & 31, wid = tid >> 5;
    const int nCta = gridDim.x;
    const float sh = sp[0], bi = bp[0];
    const size_t vstride = term ? (size_t)(WDIM * CDIM) : (size_t)CDIM;

    auto toff = [&](int t) -> size_t {
        int rc = t & 127, b = t >> 7;
        return term ? ((size_t)b * HDIM * WDIM * CDIM + (size_t)rc * CDIM)
                    : ((size_t)b * 128 + rc) * (size_t)(WDIM * CDIM);
    };
    auto issue_A = [&](int t, int p) {
        int rc = t & 127, b = t >> 7;
        const float* src = attn + ((size_t)b * 128 + rc) * (size_t)(128 * 128);
        #pragma unroll
        for (int i = 0; i < 8; ++i) {
            int c = i * 512 + tid;                   // 4096 16B chunks
            int row = c >> 5, q = c & 31;
            cp16(Au[p] + (uint32_t)row * (A_STRIDE * 4) + (uint32_t)q * 16,
                 src + row * 128 + q * 4);
        }
        CP_COMMIT();
    };
    auto issue_B = [&](int t, int chunk) {
        const float* src = V + toff(t) + (size_t)(chunk * KCHUNK) * vstride;
        const uint32_t dst = Bu + (uint32_t)(chunk & 3) * (B_WORDS * 4);
        #pragma unroll
        for (int i = 0; i < 2; ++i) {
            int c = i * 512 + tid;                   // 1024 16B chunks: 16 rows x 64 q
            int row = c >> 6, q = c & 63;
            cp16(dst + (uint32_t)row * (B_STRIDE * 4) + (uint32_t)q * 16,
                 src + (size_t)row * vstride + q * 4);
        }
        CP_COMMIT();
    };

    int t = blockIdx.x;
    if (t >= ntiles) return;

    int p = 0;
    issue_A(t, 0);
    issue_B(t, 0);
    issue_B(t, 1);
    issue_B(t, 2);

    const int mh = (wid & 1) * 64;
    const int nq = (wid >> 1) * 32;
    const int lr = lane >> 2, lc = lane & 3;
    const int lm_mat = lane >> 3, lm_row = lane & 7;
    const int lm_roff = (lm_mat & 1) * 8 + lm_row;
    const int lm_koff = (lm_mat >> 1) * 4;

    #pragma unroll 1
    for (; t < ntiles; t += nCta) {
        const bool last = (t + nCta >= ntiles);
        const size_t off = toff(t);

        // ---- head: A(t) ready ----
        CP_WAIT(3);
        __syncthreads();

        // L2 prefetch of the RMW out tile (term 2)
        if (term) {
            const float* ob = out + off;
            #pragma unroll
            for (int i = 0; i < 2; ++i) {
                int idx = i * 512 + tid;             // 1024 x 128B lines
                int row = idx >> 3, lq = idx & 7;
                asm volatile("prefetch.global.L2 [%0];"
                             :: "l"(ob + (size_t)row * vstride + lq * 32));
            }
        }

        // ---- softmax in place (no max pass; exponents bounded ~e^9) ----
        float* Af = (float*)Ab[p];
        #pragma unroll 1
        for (int rr = 0; rr < 8; ++rr) {
            int row = wid * 8 + rr;
            float4 v = *(const float4*)(Af + row * A_STRIDE + lane * 4);
            float fr = (float)row;
            float e[4]; float s = 0.f;
            #pragma unroll
            for (int j = 0; j < 4; ++j) {
                float d = (float)(lane * 4 + j) - fr;
                float vv = (j == 0 ? v.x : j == 1 ? v.y : j == 2 ? v.z : v.w)
                           - fmaf(sh, d * d, bi);
                e[j] = __expf(vv);
                s += e[j];
            }
            #pragma unroll
            for (int o = 16; o > 0; o >>= 1) s += __shfl_xor_sync(~0u, s, o);
            float inv = 1.0f / s;
            uint4 w = make_uint4(tf32u(e[0] * inv), tf32u(e[1] * inv),
                                 tf32u(e[2] * inv), tf32u(e[3] * inv));
            *(uint4*)(Ab[p] + row * A_STRIDE + lane * 4) = w;
        }
        __syncthreads();

        if (!last) issue_A(t + nCta, p ^ 1);

        float acc[4][4][4];
        #pragma unroll
        for (int u = 0; u < 4; ++u)
            #pragma unroll
            for (int j = 0; j < 4; ++j)
                #pragma unroll
                for (int q = 0; q < 4; ++q) acc[u][j][q] = 0.f;

        // ---- 8 k-chunks of 16, 4-buffer ring ----
        #pragma unroll 1
        for (int c = 0; c < NCHUNK; ++c) {
            if (!last) {
                if (c <= 2) CP_WAIT(3); else CP_WAIT(2);
            } else {
                if (c <= 5) CP_WAIT(2);
                else if (c == 6) CP_WAIT(1);
                else CP_WAIT(0);
            }
            __syncthreads();     // B_c ready; all warps past chunk c-1 (frees buf (c+3)%4)

            // issue 3 chunks ahead
            if (c <= 4) issue_B(t, c + 3);
            else if (!last) issue_B(t + nCta, c - 5);

            const uint32_t* Bsc = Bb + (c & 3) * B_WORDS;
            #pragma unroll
            for (int ks = 0; ks < 2; ++ks) {
                uint32_t a[4][4];
                #pragma unroll
                for (int u = 0; u < 4; ++u) {
                    uint32_t addr = Au[p] + (uint32_t)((mh + u * 16 + lm_roff) * A_STRIDE
                                                       + c * KCHUNK + ks * 8 + lm_koff) * 4;
                    ldsm_x4(a[u], addr);
                }
                #pragma unroll
                for (int j = 0; j < 4; ++j) {
                    const float* bp8 = (const float*)Bsc + (ks * 8 + lc) * B_STRIDE
                                       + nq + j * 8 + lr;
                    uint32_t b0 = tf32u(bp8[0]);
                    uint32_t b1 = tf32u(bp8[4 * B_STRIDE]);
                    #pragma unroll
                    for (int u = 0; u < 4; ++u)
                        mma_tf32(acc[u][j], a[u], b0, b1);
                }
            }
        }

        // ---- epilogue ----
        float* obase = out + off;
        #pragma unroll
        for (int u = 0; u < 4; ++u) {
            #pragma unroll
            for (int j = 0; j < 4; ++j) {
                int r0 = mh + u * 16 + lr;
                int col = nq + j * 8 + lc * 2;
                float* p0 = obase + (size_t)r0 * vstride + col;
                float* p1 = p0 + 8 * vstride;
                float2 v0 = make_float2(acc[u][j][0], acc[u][j][1]);
                float2 v1 = make_float2(acc[u][j][2], acc[u][j][3]);
                if (term) {
                    float2 c0 = *(float2*)p0, c1 = *(float2*)p1;
                    v0.x += c0.x; v0.y += c0.y;
                    v1.x += c1.x; v1.y += c1.y;
                }
                *(float2*)p0 = v0;
                *(float2*)p1 = v1;
            }
        }

        p ^= 1;
    }
}

extern "C" void kernel_launch(void* const* d_in, const int* in_sizes, int n_in,
                              void* d_out, int out_size)
{
    const float* attn_x = (const float*)d_in[1];
    const float* attn_y = (const float*)d_in[2];
    const float* V      = (const float*)d_in[3];
    const float* sh     = (const float*)d_in[4];
    const float* bi     = (const float*)d_in[5];
    float* out          = (float*)d_out;

    const int B = in_sizes[3] / (HDIM * WDIM * CDIM);
    const int ntiles = B * 128;

    int nsm = 148;
    cudaDeviceGetAttribute(&nsm, cudaDevAttrMultiProcessorCount, 0);
    int grid = nsm < ntiles ? nsm : ntiles;

    cudaFuncSetAttribute(gt_mma, cudaFuncAttributeMaxDynamicSharedMemorySize, SMEM_BYTES);

    gt_mma<<<grid, 512, SMEM_BYTES>>>(attn_x, V, sh, bi, out, 0, ntiles);
    gt_mma<<<grid, 512, SMEM_BYTES>>>(attn_y, V, sh, bi, out, 1, ntiles);
}